// round 1
// baseline (speedup 1.0000x reference)
#include <cuda_runtime.h>

// Problem: VQ nearest-codebook lookup.
//   z_e_x: [16, 2048, 256] f32  -> N = 32768 rows, D = 256
//   embedding: [1024, 256] f32  -> K = 1024 codes
// Outputs (flattened into d_out as f32):
//   z_q_x      : N*D   floats at offset 0
//   z_q_x_bar  : N*D   floats at offset 8388608
//   indices    : N     floats at offset 16777216
//
// argmin_k ( ||c_k||^2 - 2 x.c_k )  (the ||x||^2 term is row-constant).

#define NTOK   32768
#define DDIM   256
#define KCODE  1024
#define BM     128          // rows per block
#define BN     128          // codes per tile
#define KCH    16           // k-depth per smem stage
#define XPAD   132          // BM + 4 padding (keeps float4 alignment, kills conflicts)

#define OUT_BAR   8388608   // N*D
#define OUT_IDX  16777216   // 2*N*D

__device__ float g_cnorm[KCODE];

// ---------------------------------------------------------------------------
// Per-code squared norm: one warp per code.
// ---------------------------------------------------------------------------
__global__ void cnorm_kernel(const float* __restrict__ emb) {
    int warp = (blockIdx.x * blockDim.x + threadIdx.x) >> 5;
    int lane = threadIdx.x & 31;
    if (warp >= KCODE) return;
    const float* row = emb + (size_t)warp * DDIM;
    float s = 0.f;
    #pragma unroll
    for (int k = lane; k < DDIM; k += 32) { float v = row[k]; s += v * v; }
    #pragma unroll
    for (int o = 16; o; o >>= 1) s += __shfl_xor_sync(0xffffffffu, s, o);
    if (lane == 0) g_cnorm[warp] = s;
}

// ---------------------------------------------------------------------------
// Fused distance-GEMM + argmin + gather kernel.
// Block: 256 threads = 16(tx: codes) x 16(ty: rows). 8x8 micro-tile (4+4 split).
// ---------------------------------------------------------------------------
__global__ __launch_bounds__(256, 1)
void vq_kernel(const float* __restrict__ x,
               const float* __restrict__ emb,
               float* __restrict__ out) {
    __shared__ float Xs[2][KCH][XPAD];
    __shared__ float Cs[2][KCH][XPAD];
    __shared__ float cns[BN];
    __shared__ int   bidx_s[BM];

    const int tid = threadIdx.x;
    const int tx  = tid & 15;
    const int ty  = tid >> 4;
    const int rowBase = blockIdx.x * BM;

    // loader mapping: thread owns rows m0 and m0+64 at k-offset q0 (float4 each)
    const int m0 = tid >> 2;
    const int q0 = (tid & 3) * 4;

    float bestV[8];
    int   bestI[8];
    #pragma unroll
    for (int i = 0; i < 8; ++i) { bestV[i] = 3.4e38f; bestI[i] = 0; }

    float4 nx0, nx1, nc0, nc1;

    for (int t = 0; t < KCODE / BN; ++t) {
        const int cb = t * BN;
        if (tid < BN) cns[tid] = g_cnorm[cb + tid];

        float acc[8][8];
        #pragma unroll
        for (int i = 0; i < 8; ++i)
            #pragma unroll
            for (int j = 0; j < 8; ++j) acc[i][j] = 0.f;

        // ---- prologue: stage 0 ----
        {
            const int kg = q0;  // chunk 0
            nx0 = *(const float4*)&x[(size_t)(rowBase + m0)      * DDIM + kg];
            nx1 = *(const float4*)&x[(size_t)(rowBase + m0 + 64) * DDIM + kg];
            nc0 = *(const float4*)&emb[(size_t)(cb + m0)      * DDIM + kg];
            nc1 = *(const float4*)&emb[(size_t)(cb + m0 + 64) * DDIM + kg];
            Xs[0][q0+0][m0] = nx0.x; Xs[0][q0+1][m0] = nx0.y; Xs[0][q0+2][m0] = nx0.z; Xs[0][q0+3][m0] = nx0.w;
            Xs[0][q0+0][m0+64] = nx1.x; Xs[0][q0+1][m0+64] = nx1.y; Xs[0][q0+2][m0+64] = nx1.z; Xs[0][q0+3][m0+64] = nx1.w;
            Cs[0][q0+0][m0] = nc0.x; Cs[0][q0+1][m0] = nc0.y; Cs[0][q0+2][m0] = nc0.z; Cs[0][q0+3][m0] = nc0.w;
            Cs[0][q0+0][m0+64] = nc1.x; Cs[0][q0+1][m0+64] = nc1.y; Cs[0][q0+2][m0+64] = nc1.z; Cs[0][q0+3][m0+64] = nc1.w;
        }
        __syncthreads();

        const int S = DDIM / KCH;  // 16 stages
        for (int s = 0; s < S; ++s) {
            const int cur = s & 1;
            if (s + 1 < S) {
                const int kg = (s + 1) * KCH + q0;
                nx0 = *(const float4*)&x[(size_t)(rowBase + m0)      * DDIM + kg];
                nx1 = *(const float4*)&x[(size_t)(rowBase + m0 + 64) * DDIM + kg];
                nc0 = *(const float4*)&emb[(size_t)(cb + m0)      * DDIM + kg];
                nc1 = *(const float4*)&emb[(size_t)(cb + m0 + 64) * DDIM + kg];
            }
            #pragma unroll
            for (int k = 0; k < KCH; ++k) {
                float4 a0 = *(const float4*)&Xs[cur][k][ty * 4];
                float4 a1 = *(const float4*)&Xs[cur][k][64 + ty * 4];
                float4 b0 = *(const float4*)&Cs[cur][k][tx * 4];
                float4 b1 = *(const float4*)&Cs[cur][k][64 + tx * 4];
                float a[8] = {a0.x, a0.y, a0.z, a0.w, a1.x, a1.y, a1.z, a1.w};
                float b[8] = {b0.x, b0.y, b0.z, b0.w, b1.x, b1.y, b1.z, b1.w};
                #pragma unroll
                for (int i = 0; i < 8; ++i)
                    #pragma unroll
                    for (int j = 0; j < 8; ++j)
                        acc[i][j] = fmaf(a[i], b[j], acc[i][j]);
            }
            __syncthreads();
            if (s + 1 < S) {
                const int nb = (s + 1) & 1;
                Xs[nb][q0+0][m0] = nx0.x; Xs[nb][q0+1][m0] = nx0.y; Xs[nb][q0+2][m0] = nx0.z; Xs[nb][q0+3][m0] = nx0.w;
                Xs[nb][q0+0][m0+64] = nx1.x; Xs[nb][q0+1][m0+64] = nx1.y; Xs[nb][q0+2][m0+64] = nx1.z; Xs[nb][q0+3][m0+64] = nx1.w;
                Cs[nb][q0+0][m0] = nc0.x; Cs[nb][q0+1][m0] = nc0.y; Cs[nb][q0+2][m0] = nc0.z; Cs[nb][q0+3][m0] = nc0.w;
                Cs[nb][q0+0][m0+64] = nc1.x; Cs[nb][q0+1][m0+64] = nc1.y; Cs[nb][q0+2][m0+64] = nc1.z; Cs[nb][q0+3][m0+64] = nc1.w;
                __syncthreads();
            }
        }

        // ---- epilogue: scores + argmin for this code tile ----
        #pragma unroll
        for (int i = 0; i < 8; ++i) {
            float v = 3.4e38f;
            int idx = 0x7fffffff;
            #pragma unroll
            for (int j = 0; j < 8; ++j) {
                int lc = (j < 4) ? (tx * 4 + j) : (64 + tx * 4 + (j - 4));
                float sc = fmaf(-2.0f, acc[i][j], cns[lc]);
                int gc = cb + lc;
                if (sc < v) { v = sc; idx = gc; }
            }
            // min-reduce across the 16 code-lanes (same ty group), first-index ties
            #pragma unroll
            for (int o = 1; o < 16; o <<= 1) {
                float vo = __shfl_xor_sync(0xffffffffu, v, o, 16);
                int   io = __shfl_xor_sync(0xffffffffu, idx, o, 16);
                if (vo < v || (vo == v && io < idx)) { v = vo; idx = io; }
            }
            if (v < bestV[i] || (v == bestV[i] && idx < bestI[i])) {
                bestV[i] = v; bestI[i] = idx;
            }
        }
        __syncthreads();  // protect cns / smem buffers before next tile
    }

    // ---- publish per-row winners ----
    if (tx == 0) {
        #pragma unroll
        for (int i = 0; i < 8; ++i) {
            int m = (i < 4) ? (ty * 4 + i) : (64 + ty * 4 + (i - 4));
            bidx_s[m] = bestI[i];
        }
    }
    __syncthreads();

    // ---- gather codes and write outputs (block-cooperative, float4) ----
    const float4* emb4 = (const float4*)emb;
    float4* o4 = (float4*)out;
    #pragma unroll 4
    for (int it = 0; it < 32; ++it) {
        int g = tid + it * 256;          // 0..8191
        int m = g >> 6;                  // row within block (0..127)
        int q = g & 63;                  // float4 index within row
        int code = bidx_s[m];
        float4 v = emb4[(size_t)code * 64 + q];
        size_t off = (size_t)(rowBase + m) * 64 + q;
        o4[off] = v;                      // z_q_x
        o4[off + (OUT_BAR / 4)] = v;      // z_q_x_bar
    }
    if (tid < BM) out[OUT_IDX + rowBase + tid] = (float)bidx_s[tid];
}

// ---------------------------------------------------------------------------
extern "C" void kernel_launch(void* const* d_in, const int* in_sizes, int n_in,
                              void* d_out, int out_size) {
    const float* x   = (const float*)d_in[0];   // z_e_x [16,2048,256]
    const float* emb = (const float*)d_in[1];   // embedding [1024,256]
    float* out = (float*)d_out;

    cnorm_kernel<<<KCODE / 8, 256>>>(emb);
    vq_kernel<<<NTOK / BM, 256>>>(x, emb, out);
}

// round 2
// speedup vs baseline: 1.0687x; 1.0687x over previous
#include <cuda_runtime.h>

// VQ nearest-codebook lookup, f32x2-packed distance GEMM.
//   z_e_x: [16,2048,256] f32 -> N=32768 rows, D=256
//   embedding: [1024,256] f32 -> K=1024 codes
// d_out (f32): z_q_x [N*D] @0, z_q_x_bar [N*D] @8388608, indices [N] @16777216
// argmin_k ( ||c_k||^2 - 2 x.c_k )

#define NTOK   32768
#define DDIM   256
#define KCODE  1024
#define BM     128
#define BN     256
#define KCH    8
#define XPAD   132          // 128 + 4, 16B-aligned row stride
#define CPAD   264          // 256 + 8, 16B-aligned row stride

#define OUT_BAR   8388608
#define OUT_IDX  16777216

typedef unsigned long long u64;

__device__ float g_cnorm[KCODE];

// ---------------------------------------------------------------------------
__global__ void cnorm_kernel(const float* __restrict__ emb) {
    int warp = (blockIdx.x * blockDim.x + threadIdx.x) >> 5;
    int lane = threadIdx.x & 31;
    if (warp >= KCODE) return;
    const float* row = emb + (size_t)warp * DDIM;
    float s = 0.f;
    #pragma unroll
    for (int k = lane; k < DDIM; k += 32) { float v = row[k]; s += v * v; }
    #pragma unroll
    for (int o = 16; o; o >>= 1) s += __shfl_xor_sync(0xffffffffu, s, o);
    if (lane == 0) g_cnorm[warp] = s;
}

// ---------------------------------------------------------------------------
__device__ __forceinline__ void ffma2(u64& d, u64 a, u64 b) {
    asm("fma.rn.f32x2 %0, %1, %2, %0;" : "+l"(d) : "l"(a), "l"(b));
}
__device__ __forceinline__ u64 swap64(u64 v) {
    u64 r;
    asm("{\n\t.reg .b32 lo, hi;\n\tmov.b64 {lo, hi}, %1;\n\tmov.b64 %0, {hi, lo};\n\t}"
        : "=l"(r) : "l"(v));
    return r;
}
__device__ __forceinline__ float lo32(u64 v) { return __uint_as_float((unsigned)v); }
__device__ __forceinline__ float hi32(u64 v) { return __uint_as_float((unsigned)(v >> 32)); }

__device__ __forceinline__ void upd(float& bv, int& bi, float s, int c) {
    if (s < bv || (s == bv && c < bi)) { bv = s; bi = c; }
}

// ---------------------------------------------------------------------------
// 256 threads = 16(tx: code groups) x 16(ty: row groups).
// Per thread: 8 rows x 16 codes via packed f32x2 outer product (accD/accX).
__global__ __launch_bounds__(256, 1)
void vq_kernel(const float* __restrict__ x,
               const float* __restrict__ emb,
               float* __restrict__ out) {
    __shared__ float Xs[2][KCH][XPAD];   // k-major: Xs[k][row]
    __shared__ float Cs[2][KCH][CPAD];   // k-major: Cs[k][code]
    __shared__ float cns_s[BN];
    __shared__ int   bidx_s[BM];

    const int tid = threadIdx.x;
    const int tx  = tid & 15;
    const int ty  = tid >> 4;
    const int rowBase = blockIdx.x * BM;

    // loader mapping
    const int lm = tid >> 1;             // Xs row 0..127
    const int lq = (tid & 1) * 4;        // Xs k offset 0 or 4
    const float* xrow = x + (size_t)(rowBase + lm) * DDIM + lq;

    float bestV[8];
    int   bestI[8];
    #pragma unroll
    for (int i = 0; i < 8; ++i) { bestV[i] = 3.4e38f; bestI[i] = 0x7fffffff; }

    for (int t = 0; t < KCODE / BN; ++t) {
        const int cb = t * BN;
        __syncthreads();                 // previous tile's epilogue done with cns_s
        cns_s[tid] = g_cnorm[cb + tid];

        u64 accD[4][8], accX[4][8];
        #pragma unroll
        for (int p = 0; p < 4; ++p)
            #pragma unroll
            for (int q = 0; q < 8; ++q) { accD[p][q] = 0ull; accX[p][q] = 0ull; }

        const float* crow = emb + (size_t)(cb + tid) * DDIM;

        // ---- prologue: stage 0 ----
        float4 pX  = *(const float4*)(xrow);
        float4 pC0 = *(const float4*)(crow);
        float4 pC1 = *(const float4*)(crow + 4);
        Xs[0][lq+0][lm] = pX.x; Xs[0][lq+1][lm] = pX.y;
        Xs[0][lq+2][lm] = pX.z; Xs[0][lq+3][lm] = pX.w;
        Cs[0][0][tid] = pC0.x; Cs[0][1][tid] = pC0.y;
        Cs[0][2][tid] = pC0.z; Cs[0][3][tid] = pC0.w;
        Cs[0][4][tid] = pC1.x; Cs[0][5][tid] = pC1.y;
        Cs[0][6][tid] = pC1.z; Cs[0][7][tid] = pC1.w;
        __syncthreads();

        const int S = DDIM / KCH;        // 32 stages
        for (int s = 0; s < S; ++s) {
            const int cur = s & 1;
            if (s + 1 < S) {
                const int kg = (s + 1) * KCH;
                pX  = *(const float4*)(xrow + kg);
                pC0 = *(const float4*)(crow + kg);
                pC1 = *(const float4*)(crow + kg + 4);
            }
            #pragma unroll
            for (int k = 0; k < KCH; ++k) {
                ulonglong2 aA = *(const ulonglong2*)&Xs[cur][k][ty * 4];
                ulonglong2 aB = *(const ulonglong2*)&Xs[cur][k][64 + ty * 4];
                u64 ap[4] = {aA.x, aA.y, aB.x, aB.y};
                u64 bp[8], bs[8];
                #pragma unroll
                for (int g = 0; g < 4; ++g) {
                    ulonglong2 bb = *(const ulonglong2*)&Cs[cur][k][tx * 4 + 64 * g];
                    bp[2*g]   = bb.x;         bp[2*g+1] = bb.y;
                    bs[2*g]   = swap64(bb.x); bs[2*g+1] = swap64(bb.y);
                }
                #pragma unroll
                for (int p = 0; p < 4; ++p)
                    #pragma unroll
                    for (int q = 0; q < 8; ++q) {
                        ffma2(accD[p][q], ap[p], bp[q]);
                        ffma2(accX[p][q], ap[p], bs[q]);
                    }
            }
            __syncthreads();
            if (s + 1 < S) {
                const int nb = (s + 1) & 1;
                Xs[nb][lq+0][lm] = pX.x; Xs[nb][lq+1][lm] = pX.y;
                Xs[nb][lq+2][lm] = pX.z; Xs[nb][lq+3][lm] = pX.w;
                Cs[nb][0][tid] = pC0.x; Cs[nb][1][tid] = pC0.y;
                Cs[nb][2][tid] = pC0.z; Cs[nb][3][tid] = pC0.w;
                Cs[nb][4][tid] = pC1.x; Cs[nb][5][tid] = pC1.y;
                Cs[nb][6][tid] = pC1.z; Cs[nb][7][tid] = pC1.w;
                __syncthreads();
            }
        }

        // ---- epilogue: scores + per-row argmin for this tile ----
        #pragma unroll
        for (int p = 0; p < 4; ++p) {
            #pragma unroll
            for (int q = 0; q < 8; ++q) {
                int lc0 = tx * 4 + 64 * (q >> 1) + 2 * (q & 1);
                int c0  = cb + lc0;
                float n0 = cns_s[lc0], n1 = cns_s[lc0 + 1];
                float sLo0 = fmaf(-2.f, lo32(accD[p][q]), n0);  // row_lo . c0
                float sHi1 = fmaf(-2.f, hi32(accD[p][q]), n1);  // row_hi . c1
                float sLo1 = fmaf(-2.f, lo32(accX[p][q]), n1);  // row_lo . c1
                float sHi0 = fmaf(-2.f, hi32(accX[p][q]), n0);  // row_hi . c0
                upd(bestV[2*p],   bestI[2*p],   sLo0, c0);
                upd(bestV[2*p],   bestI[2*p],   sLo1, c0 + 1);
                upd(bestV[2*p+1], bestI[2*p+1], sHi0, c0);
                upd(bestV[2*p+1], bestI[2*p+1], sHi1, c0 + 1);
            }
        }
    }

    // ---- reduce across the 16 code-lanes (same ty group) ----
    #pragma unroll
    for (int i = 0; i < 8; ++i) {
        float v = bestV[i]; int idx = bestI[i];
        #pragma unroll
        for (int o = 1; o < 16; o <<= 1) {
            float vo = __shfl_xor_sync(0xffffffffu, v,   o, 16);
            int   io = __shfl_xor_sync(0xffffffffu, idx, o, 16);
            if (vo < v || (vo == v && io < idx)) { v = vo; idx = io; }
        }
        bestV[i] = v; bestI[i] = idx;
    }
    __syncthreads();
    if (tx == 0) {
        // rows for pair p: lo = (p<2 ? ty*4+2p : 64+ty*4+2(p-2)), hi = lo+1
        #pragma unroll
        for (int p = 0; p < 4; ++p) {
            int mlo = (p < 2) ? (ty * 4 + 2 * p) : (64 + ty * 4 + 2 * (p - 2));
            bidx_s[mlo]     = bestI[2*p];
            bidx_s[mlo + 1] = bestI[2*p + 1];
        }
    }
    __syncthreads();

    // ---- gather codes and write outputs ----
    const float4* emb4 = (const float4*)emb;
    float4* o4 = (float4*)out;
    #pragma unroll 4
    for (int it = 0; it < 32; ++it) {
        int g = tid + it * 256;
        int m = g >> 6;
        int qq = g & 63;
        int code = bidx_s[m];
        float4 v = emb4[(size_t)code * 64 + qq];
        size_t off = (size_t)(rowBase + m) * 64 + qq;
        o4[off] = v;
        o4[off + (OUT_BAR / 4)] = v;
    }
    if (tid < BM) out[OUT_IDX + rowBase + tid] = (float)bidx_s[tid];
}

// ---------------------------------------------------------------------------
extern "C" void kernel_launch(void* const* d_in, const int* in_sizes, int n_in,
                              void* d_out, int out_size) {
    const float* x   = (const float*)d_in[0];
    const float* emb = (const float*)d_in[1];
    float* out = (float*)d_out;

    cnorm_kernel<<<KCODE / 8, 256>>>(emb);
    vq_kernel<<<NTOK / BM, 256>>>(x, emb, out);
}

// round 4
// speedup vs baseline: 1.2785x; 1.1963x over previous
#include <cuda_runtime.h>
#include <cstdint>

// VQ nearest-codebook lookup via 3xTF32 mma.sync distance GEMM.
//   z_e_x: [16,2048,256] f32 -> N=32768 rows, D=256
//   embedding: [1024,256] f32 -> K=1024 codes
// d_out (f32): z_q_x [N*D] @0, z_q_x_bar [N*D] @8388608, indices [N] @16777216
// argmin_k(||c||^2 - 2 x.c) == argmax_k(x.c - ||c||^2/2); the norm term is
// folded into the GEMM as an extra k8 chunk.

#define NTOK   32768
#define DDIM   256
#define KCODE  1024
#define BM     256          // rows per CTA
#define BN     128          // codes per tile
#define KS     16           // k per stage
#define NST    16           // stages per tile
#define NTILE  8            // KCODE / BN
#define PITCH  20           // floats per k16 row (80B, bank-clean for ldmatrix)

#define OUT_BAR   8388608
#define OUT_IDX  16777216

// float offsets into dynamic smem
#define AH_F      0         // [256][20]
#define AL_F   5120
#define BH_F  10240         // [128][20]
#define BL_F  12800
#define AC_F  15360         // A-ones chunk [256][8]
#define BCH_F 17408         // -cnorm/2 hi [128][8]
#define BCL_F 18432
#define DYN_FLOATS 19456
#define DYN_SMEM (DYN_FLOATS * 4)

__device__ float g_cnorm[KCODE];

// ---------------------------------------------------------------------------
__device__ __forceinline__ uint32_t smem_u32(const void* p) {
    uint32_t a;
    asm("{ .reg .u64 t; cvta.to.shared.u64 t, %1; cvt.u32.u64 %0, t; }"
        : "=r"(a) : "l"(p));
    return a;
}
__device__ __forceinline__ float tf32_rna(float x) {
    uint32_t r;
    asm("cvt.rna.tf32.f32 %0, %1;" : "=r"(r) : "f"(x));
    return __uint_as_float(r);
}
#define LDSM4(r, addr) \
    asm volatile("ldmatrix.sync.aligned.m8n8.x4.shared.b16 {%0,%1,%2,%3}, [%4];" \
        : "=r"((r)[0]), "=r"((r)[1]), "=r"((r)[2]), "=r"((r)[3]) : "r"(addr))

__device__ __forceinline__ void mma_tf32(float* c, const uint32_t* a, const uint32_t* b) {
    asm volatile(
        "mma.sync.aligned.m16n8k8.row.col.f32.tf32.tf32.f32 "
        "{%0,%1,%2,%3}, {%4,%5,%6,%7}, {%8,%9}, {%0,%1,%2,%3};"
        : "+f"(c[0]), "+f"(c[1]), "+f"(c[2]), "+f"(c[3])
        : "r"(a[0]), "r"(a[1]), "r"(a[2]), "r"(a[3]), "r"(b[0]), "r"(b[1]));
}

// ---------------------------------------------------------------------------
__global__ void cnorm_kernel(const float* __restrict__ emb) {
    int warp = (blockIdx.x * blockDim.x + threadIdx.x) >> 5;
    int lane = threadIdx.x & 31;
    if (warp >= KCODE) return;
    const float* row = emb + (size_t)warp * DDIM;
    float s = 0.f;
    #pragma unroll
    for (int k = lane; k < DDIM; k += 32) { float v = row[k]; s += v * v; }
    #pragma unroll
    for (int o = 16; o; o >>= 1) s += __shfl_xor_sync(0xffffffffu, s, o);
    if (lane == 0) g_cnorm[warp] = s;
}

// ---------------------------------------------------------------------------
// 256 threads = 8 warps in 4(m) x 2(n); warp tile 64 rows x 64 codes.
// ---------------------------------------------------------------------------
__global__ __launch_bounds__(256)
void vq_mma_kernel(const float* __restrict__ x,
                   const float* __restrict__ emb,
                   float* __restrict__ out) {
    extern __shared__ float dsm[];
    __shared__ float sV[2][BM];
    __shared__ int   sI[2][BM];
    __shared__ int   bidx_s[BM];

    const int tid = threadIdx.x;
    const int wid = tid >> 5;
    const int L   = tid & 31;
    const int rowBase = blockIdx.x * BM;
    const int mbase = (wid >> 1) * 64;
    const int nbase = (wid & 1) * 64;

    const uint32_t SB   = smem_u32(dsm);
    const uint32_t AH_B = SB + AH_F * 4;
    const uint32_t AL_B = SB + AL_F * 4;
    const uint32_t BH_B = SB + BH_F * 4;
    const uint32_t BL_B = SB + BL_F * 4;
    const uint32_t AC_B = SB + AC_F * 4;
    const uint32_t BCH_B = SB + BCH_F * 4;
    const uint32_t BCL_B = SB + BCL_F * 4;

    // lane geometry for ldmatrix fragment addressing (byte offsets)
    const int aRow = (L & 7) + 8 * ((L >> 3) & 1);
    const int aK   = (L >> 4) * 16;
    const int bRow = (L & 7) + 8 * ((L >> 4) & 1);
    const int bK   = ((L >> 3) & 1) * 16;
    const uint32_t aBase = (uint32_t)((mbase + aRow) * 80 + aK);
    const uint32_t bBase = (uint32_t)((nbase + bRow) * 80 + bK);
    const uint32_t acBase = (uint32_t)((mbase + aRow) * 32 + aK);
    const uint32_t bcBase = (uint32_t)((nbase + bRow) * 32 + bK);

    // loader geometry
    const int lRow = tid >> 2;          // 0..63
    const int lKg  = tid & 3;           // float4 slot within k16

    // init constant chunks: A-ones (k=0 -> 1), Bc zeros
    for (int i = tid; i < 2048; i += 256) dsm[AC_F + i] = ((i & 7) == 0) ? 1.f : 0.f;
    for (int i = tid; i < 1024; i += 256) { dsm[BCH_F + i] = 0.f; dsm[BCL_F + i] = 0.f; }

    float bV[8];
    int   bI[8];
    #pragma unroll
    for (int i = 0; i < 8; ++i) { bV[i] = -3.4e38f; bI[i] = 0x7fffffff; }

    float4 vA[4], vB[2];

    for (int t = 0; t < NTILE; ++t) {
        const int cb = t * BN;
        __syncthreads();                           // prev tile done reading Bc
        if (tid < BN) {
            float m = -0.5f * g_cnorm[cb + tid];
            float h = tf32_rna(m);
            dsm[BCH_F + tid * 8] = h;
            dsm[BCL_F + tid * 8] = tf32_rna(m - h);
        }

        float acc[4][8][4];
        #pragma unroll
        for (int f = 0; f < 4; ++f)
            #pragma unroll
            for (int n = 0; n < 8; ++n)
                #pragma unroll
                for (int e = 0; e < 4; ++e) acc[f][n][e] = 0.f;

        #define LOAD_STAGE(s) do { \
            const float* xp = x + (size_t)(rowBase + lRow) * DDIM + (s) * KS + lKg * 4; \
            vA[0] = *(const float4*)(xp); \
            vA[1] = *(const float4*)(xp +  64 * DDIM); \
            vA[2] = *(const float4*)(xp + 128 * DDIM); \
            vA[3] = *(const float4*)(xp + 192 * DDIM); \
            const float* bp = emb + (size_t)(cb + lRow) * DDIM + (s) * KS + lKg * 4; \
            vB[0] = *(const float4*)(bp); \
            vB[1] = *(const float4*)(bp + 64 * DDIM); \
        } while (0)

        #define SPLIT_STORE() do { \
            _Pragma("unroll") \
            for (int i = 0; i < 4; ++i) { \
                float4 v = vA[i]; float4 h, l; \
                h.x = tf32_rna(v.x); l.x = tf32_rna(v.x - h.x); \
                h.y = tf32_rna(v.y); l.y = tf32_rna(v.y - h.y); \
                h.z = tf32_rna(v.z); l.z = tf32_rna(v.z - h.z); \
                h.w = tf32_rna(v.w); l.w = tf32_rna(v.w - h.w); \
                int r = lRow + 64 * i; \
                *(float4*)&dsm[AH_F + r * PITCH + lKg * 4] = h; \
                *(float4*)&dsm[AL_F + r * PITCH + lKg * 4] = l; \
            } \
            _Pragma("unroll") \
            for (int i = 0; i < 2; ++i) { \
                float4 v = vB[i]; float4 h, l; \
                h.x = tf32_rna(v.x); l.x = tf32_rna(v.x - h.x); \
                h.y = tf32_rna(v.y); l.y = tf32_rna(v.y - h.y); \
                h.z = tf32_rna(v.z); l.z = tf32_rna(v.z - h.z); \
                h.w = tf32_rna(v.w); l.w = tf32_rna(v.w - h.w); \
                int r = lRow + 64 * i; \
                *(float4*)&dsm[BH_F + r * PITCH + lKg * 4] = h; \
                *(float4*)&dsm[BL_F + r * PITCH + lKg * 4] = l; \
            } \
        } while (0)

        LOAD_STAGE(0);
        SPLIT_STORE();
        __syncthreads();

        for (int s = 0; s < NST; ++s) {
            if (s + 1 < NST) LOAD_STAGE(s + 1);
            #pragma unroll
            for (int kk = 0; kk < 2; ++kk) {
                const uint32_t kof = (uint32_t)(kk * 32);
                uint32_t ah[4][4], bh[4][4];
                #pragma unroll
                for (int f = 0; f < 4; ++f) LDSM4(ah[f], AH_B + aBase + f * 1280 + kof);
                #pragma unroll
                for (int g = 0; g < 4; ++g) LDSM4(bh[g], BH_B + bBase + g * 1280 + kof);
                #pragma unroll
                for (int f = 0; f < 4; ++f)
                    #pragma unroll
                    for (int n = 0; n < 8; ++n)
                        mma_tf32(acc[f][n], ah[f], &bh[n >> 1][(n & 1) * 2]);
                {
                    uint32_t bl[4][4];
                    #pragma unroll
                    for (int g = 0; g < 4; ++g) LDSM4(bl[g], BL_B + bBase + g * 1280 + kof);
                    #pragma unroll
                    for (int f = 0; f < 4; ++f)
                        #pragma unroll
                        for (int n = 0; n < 8; ++n)
                            mma_tf32(acc[f][n], ah[f], &bl[n >> 1][(n & 1) * 2]);
                }
                {
                    uint32_t al[4][4];
                    #pragma unroll
                    for (int f = 0; f < 4; ++f) LDSM4(al[f], AL_B + aBase + f * 1280 + kof);
                    #pragma unroll
                    for (int f = 0; f < 4; ++f)
                        #pragma unroll
                        for (int n = 0; n < 8; ++n)
                            mma_tf32(acc[f][n], al[f], &bh[n >> 1][(n & 1) * 2]);
                }
            }
            __syncthreads();
            if (s + 1 < NST) { SPLIT_STORE(); __syncthreads(); }
        }

        // extra k8 chunk: fold in -||c||^2/2 (A = ones, B = split cnorm)
        {
            uint32_t ao[4][4], ch[4][4], cl[4][4];
            #pragma unroll
            for (int f = 0; f < 4; ++f) LDSM4(ao[f], AC_B + acBase + f * 512);
            #pragma unroll
            for (int g = 0; g < 4; ++g) LDSM4(ch[g], BCH_B + bcBase + g * 512);
            #pragma unroll
            for (int g = 0; g < 4; ++g) LDSM4(cl[g], BCL_B + bcBase + g * 512);
            #pragma unroll
            for (int f = 0; f < 4; ++f)
                #pragma unroll
                for (int n = 0; n < 8; ++n) {
                    mma_tf32(acc[f][n], ao[f], &ch[n >> 1][(n & 1) * 2]);
                    mma_tf32(acc[f][n], ao[f], &cl[n >> 1][(n & 1) * 2]);
                }
        }

        // per-lane argmax update (ascending code order for first-min ties)
        #pragma unroll
        for (int f = 0; f < 4; ++f)
            #pragma unroll
            for (int n = 0; n < 8; ++n) {
                int c0 = cb + nbase + 8 * n + 2 * (L & 3);
                #pragma unroll
                for (int e = 0; e < 2; ++e) {
                    float vlo = acc[f][n][e];        // row lo
                    float vhi = acc[f][n][2 + e];    // row +8
                    int ci = c0 + e;
                    if (vlo > bV[2 * f])     { bV[2 * f] = vlo;     bI[2 * f] = ci; }
                    if (vhi > bV[2 * f + 1]) { bV[2 * f + 1] = vhi; bI[2 * f + 1] = ci; }
                }
            }
    }

    // quad reduce (lanes sharing L>>2 cover the same rows)
    #pragma unroll
    for (int i = 0; i < 8; ++i) {
        float v = bV[i]; int idx = bI[i];
        #pragma unroll
        for (int o = 1; o < 4; o <<= 1) {
            float vo = __shfl_xor_sync(0xffffffffu, v, o);
            int   io = __shfl_xor_sync(0xffffffffu, idx, o);
            if (vo > v || (vo == v && io < idx)) { v = vo; idx = io; }
        }
        bV[i] = v; bI[i] = idx;
    }
    if ((L & 3) == 0) {
        const int wn = wid & 1;
        #pragma unroll
        for (int f = 0; f < 4; ++f)
            #pragma unroll
            for (int h = 0; h < 2; ++h) {
                int row = mbase + 16 * f + 8 * h + (L >> 2);
                sV[wn][row] = bV[2 * f + h];
                sI[wn][row] = bI[2 * f + h];
            }
    }
    __syncthreads();

    // combine the two n-warps, publish winners
    {
        float v0 = sV[0][tid], v1 = sV[1][tid];
        int   i0 = sI[0][tid], i1 = sI[1][tid];
        int idx = (v1 > v0 || (v1 == v0 && i1 < i0)) ? i1 : i0;
        bidx_s[tid] = idx;
        out[OUT_IDX + rowBase + tid] = (float)idx;
    }
    __syncthreads();

    // gather codes, write z_q_x and z_q_x_bar
    const float4* emb4 = (const float4*)emb;
    float4* o4 = (float4*)out;
    #pragma unroll 4
    for (int it = 0; it < 64; ++it) {
        int g = tid + it * 256;          // 0..16383
        int m = g >> 6;
        int q = g & 63;
        int code = bidx_s[m];
        float4 v = emb4[(size_t)code * 64 + q];
        size_t off = (size_t)(rowBase + m) * 64 + q;
        o4[off] = v;
        o4[off + (OUT_BAR / 4)] = v;
    }
}

// ---------------------------------------------------------------------------
extern "C" void kernel_launch(void* const* d_in, const int* in_sizes, int n_in,
                              void* d_out, int out_size) {
    const float* x   = (const float*)d_in[0];
    const float* emb = (const float*)d_in[1];
    float* out = (float*)d_out;

    cudaFuncSetAttribute(vq_mma_kernel, cudaFuncAttributeMaxDynamicSharedMemorySize, DYN_SMEM);

    cnorm_kernel<<<KCODE / 8, 256>>>(emb);
    vq_mma_kernel<<<NTOK / BM, 256, DYN_SMEM>>>(x, emb, out);
}